// round 7
// baseline (speedup 1.0000x reference)
#include <cuda_runtime.h>
#include <cuda_fp16.h>
#include <cstdint>

// ---------------------------------------------------------------------------
// InteractionBlock — B=8, A=1024, N=64, F=128, S=50
// Dense layers read W fragments via LDG (L1-hot, shared across CTAs) — no W
// smem, no per-stage cp.async waits. Conv reads G/nb/mask via LDG; smem only
// for Ym (3-deep fp16 gather ring) and A_h (fp16 f_ij dbuf) -> 3 CTA/SM.
// (Round-6 source resubmitted after broker-side container failure.)
// ---------------------------------------------------------------------------

#define BA   8192
#define LN2F 0.6931471805599453f
#define APD  132     // fp32 A smem row stride (bank 4g+c, conflict-free)
#define KHP  72      // conv A_h/G row stride (halves)
#define YMS  136     // conv Ym row stride (halves)

__device__ float  g_y [BA * 128];
__device__ __half g_yh[BA * 128];
__device__ float  g_z [BA * 128];
__device__ __half g_Gt[128 * KHP];

__device__ __forceinline__ float sspf(float x) {
    return fmaxf(x, 0.f) + __logf(1.f + __expf(-fabsf(x))) - LN2F;
}
__device__ __forceinline__ float to_tf32(float x) {
    uint32_t u; asm("cvt.rna.tf32.f32 %0, %1;" : "=r"(u) : "f"(x));
    return __uint_as_float(u);
}
__device__ __forceinline__ void mma_tf32(float* d,
        uint32_t a0, uint32_t a1, uint32_t a2, uint32_t a3,
        uint32_t b0, uint32_t b1) {
    asm volatile(
        "mma.sync.aligned.m16n8k8.row.col.f32.tf32.tf32.f32 "
        "{%0,%1,%2,%3},{%4,%5,%6,%7},{%8,%9},{%0,%1,%2,%3};\n"
        : "+f"(d[0]), "+f"(d[1]), "+f"(d[2]), "+f"(d[3])
        : "r"(a0), "r"(a1), "r"(a2), "r"(a3), "r"(b0), "r"(b1));
}
__device__ __forceinline__ void mma_f16(float* d,
        uint32_t a0, uint32_t a1, uint32_t a2, uint32_t a3,
        uint32_t b0, uint32_t b1) {
    asm volatile(
        "mma.sync.aligned.m16n8k16.row.col.f32.f16.f16.f32 "
        "{%0,%1,%2,%3},{%4,%5,%6,%7},{%8,%9},{%0,%1,%2,%3};\n"
        : "+f"(d[0]), "+f"(d[1]), "+f"(d[2]), "+f"(d[3])
        : "r"(a0), "r"(a1), "r"(a2), "r"(a3), "r"(b0), "r"(b1));
}
__device__ __forceinline__ uint32_t smem_u32(const void* p) {
    return (uint32_t)__cvta_generic_to_shared(p);
}
__device__ __forceinline__ void cp16(void* dst, const void* src) {
    asm volatile("cp.async.cg.shared.global [%0], [%1], 16;\n"
                 :: "r"(smem_u32(dst)), "l"(src));
}
#define CP_COMMIT() asm volatile("cp.async.commit_group;\n")
#define CP_WAIT(n)  asm volatile("cp.async.wait_group %0;\n" :: "n"(n))

// ---------------------------------------------------------------------------
// prep: G [50,128] -> g_Gt [f][s] fp16, zero-padded to KHP.
// ---------------------------------------------------------------------------
__global__ void prep_kernel(const float* __restrict__ GW)
{
    int i = blockIdx.x * 256 + threadIdx.x;
    if (i < 128 * KHP) {
        int f = i / KHP, s = i - f * KHP;
        g_Gt[i] = (s < 50) ? __float2half_rn(GW[s * 128 + f]) : __float2half_rn(0.f);
    }
}

// ---------------------------------------------------------------------------
// tf32 warp GEMM step: 16 rows (A_s) x 32 cols (W global, LDG), K=128.
// acc[nt][4]: rows (g, g+8), cols nt*8 + c*2 {+1}.
// ---------------------------------------------------------------------------
__device__ __forceinline__ void warp_gemm16(const float* __restrict__ A_s,
                                            const float* __restrict__ Wg,
                                            int cb, int g, int c,
                                            float acc[4][4])
{
    #pragma unroll
    for (int k = 0; k < 16; k++) {
        const int kc = k * 8 + c;
        const int r0 = g * APD + kc, r1 = (g + 8) * APD + kc;
        uint32_t a0 = __float_as_uint(A_s[r0]);
        uint32_t a1 = __float_as_uint(A_s[r1]);
        uint32_t a2 = __float_as_uint(A_s[r0 + 4]);
        uint32_t a3 = __float_as_uint(A_s[r1 + 4]);
        #pragma unroll
        for (int nt = 0; nt < 4; nt++) {
            const int col = cb + nt * 8 + g;
            uint32_t b0 = __float_as_uint(__ldg(Wg + kc * 128 + col));
            uint32_t b1 = __float_as_uint(__ldg(Wg + (kc + 4) * 128 + col));
            mma_tf32(acc[nt], a0, a1, a2, a3, b0, b1);
        }
    }
}

// ---------------------------------------------------------------------------
// in2f: y = ssp( ssp(x) @ W + b ), writes fp32 y and fp16 yh.
// 16 rows/CTA, 128 threads, grid 512.
// ---------------------------------------------------------------------------
__global__ void __launch_bounds__(128)
in2f_kernel(const float* __restrict__ x, const float* __restrict__ W,
            const float* __restrict__ bias,
            float* __restrict__ y, __half* __restrict__ yh)
{
    extern __shared__ float A_s[];    // 16 x APD
    const int tid = threadIdx.x, w = tid >> 5, lane = tid & 31;
    const int g = lane >> 2, c = lane & 3;
    const int row0 = blockIdx.x * 16;

    for (int i = tid; i < 512; i += 128) {
        int r = i >> 5, c4 = (i & 31) << 2;
        float4 v = *reinterpret_cast<const float4*>(x + (size_t)(row0 + r) * 128 + c4);
        v.x = to_tf32(sspf(v.x)); v.y = to_tf32(sspf(v.y));
        v.z = to_tf32(sspf(v.z)); v.w = to_tf32(sspf(v.w));
        *reinterpret_cast<float4*>(A_s + r * APD + c4) = v;
    }
    __syncthreads();

    float acc[4][4];
    #pragma unroll
    for (int nt = 0; nt < 4; nt++)
        acc[nt][0] = acc[nt][1] = acc[nt][2] = acc[nt][3] = 0.f;
    warp_gemm16(A_s, W, w * 32, g, c, acc);

    const int r0 = row0 + g, r1 = r0 + 8;
    #pragma unroll
    for (int nt = 0; nt < 4; nt++) {
        const int f = w * 32 + nt * 8 + c * 2;
        float b0 = __ldg(bias + f), b1 = __ldg(bias + f + 1);
        float v00 = sspf(acc[nt][0] + b0);
        float v01 = sspf(acc[nt][1] + b1);
        float v10 = sspf(acc[nt][2] + b0);
        float v11 = sspf(acc[nt][3] + b1);
        y[(size_t)r0 * 128 + f]     = v00;
        y[(size_t)r0 * 128 + f + 1] = v01;
        y[(size_t)r1 * 128 + f]     = v10;
        y[(size_t)r1 * 128 + f + 1] = v11;
        *(__half2*)(yh + (size_t)r0 * 128 + f) = __floats2half2_rn(v00, v01);
        *(__half2*)(yh + (size_t)r1 * 128 + f) = __floats2half2_rn(v10, v11);
    }
}

// ---------------------------------------------------------------------------
// fused MLP: 3 residual layers + final dense.  16 rows/CTA, 128 thr, grid 512.
// Per stage: GEMM (W via LDG) -> sync -> fragment rewrite of A_s -> sync.
// ---------------------------------------------------------------------------
__global__ void __launch_bounds__(128)
mlp_kernel(const float* __restrict__ z, const float* __restrict__ resW,
           const float* __restrict__ resB, const float* __restrict__ dW,
           const float* __restrict__ dB, const float* __restrict__ mpar,
           const float* __restrict__ x, float* __restrict__ out)
{
    extern __shared__ float A_s[];    // 16 x APD
    const int tid = threadIdx.x, w = tid >> 5, lane = tid & 31;
    const int g = lane >> 2, c = lane & 3;
    const int row0 = blockIdx.x * 16;

    const float* Wp[4] = { resW, resW + 16384, resW + 32768, dW };

    for (int i = tid; i < 512; i += 128) {
        int r = i >> 5, c4 = (i & 31) << 2;
        float4 v = *reinterpret_cast<const float4*>(z + (size_t)(row0 + r) * 128 + c4);
        v.x = to_tf32(sspf(v.x)); v.y = to_tf32(sspf(v.y));
        v.z = to_tf32(sspf(v.z)); v.w = to_tf32(sspf(v.w));
        *reinterpret_cast<float4*>(A_s + r * APD + c4) = v;
    }
    __syncthreads();

    const int r0 = row0 + g, r1 = r0 + 8;

    #pragma unroll
    for (int s = 0; s < 4; s++) {
        float acc[4][4];
        #pragma unroll
        for (int nt = 0; nt < 4; nt++)
            acc[nt][0] = acc[nt][1] = acc[nt][2] = acc[nt][3] = 0.f;
        warp_gemm16(A_s, Wp[s], w * 32, g, c, acc);

        if (s < 3) {
            __syncthreads();    // all warps done reading A_s
            const float* bs = resB + s * 128;
            const int sr0 = g * APD, sr1 = sr0 + 8 * APD;
            #pragma unroll
            for (int nt = 0; nt < 4; nt++)
                #pragma unroll
                for (int e = 0; e < 2; e++) {
                    int f = w * 32 + nt * 8 + c * 2 + e;
                    float b = __ldg(bs + f);
                    float v0 = acc[nt][e] + b;
                    float v1 = acc[nt][2 + e] + b;
                    if (s == 2) {       // y = z + h3, next A = ssp(y)
                        v0 += z[(size_t)r0 * 128 + f];
                        v1 += z[(size_t)r1 * 128 + f];
                    }
                    A_s[sr0 + f] = to_tf32(sspf(v0));
                    A_s[sr1 + f] = to_tf32(sspf(v1));
                }
            __syncthreads();    // rewrite visible
        } else {
            #pragma unroll
            for (int nt = 0; nt < 4; nt++)
                #pragma unroll
                for (int e = 0; e < 2; e++) {
                    int f = w * 32 + nt * 8 + c * 2 + e;
                    float b = __ldg(dB + f), mp = __ldg(mpar + f);
                    out[(size_t)r0 * 128 + f] =
                        acc[nt][e]     + b + mp * x[(size_t)r0 * 128 + f];
                    out[(size_t)r1 * 128 + f] =
                        acc[nt][2 + e] + b + mp * x[(size_t)r1 * 128 + f];
                }
        }
    }
}

// ---------------------------------------------------------------------------
// cfconv: 16 atoms/CTA, grid 512, 128 threads, 3 CTA/SM (smem 70.6 KB).
// fp16 MMA (mask folded into A); G fragments via LDG (L1-hot); gather from
// fp16 yh 2 iterations ahead (3-buffer ring); f_ij reg-staged under MMA.
// ---------------------------------------------------------------------------
__global__ void __launch_bounds__(128)
conv_kernel(const float* __restrict__ y, const __half* __restrict__ yh,
            const int* __restrict__ nbrs, const float* __restrict__ mask,
            const float* __restrict__ fij, float* __restrict__ out)
{
    extern __shared__ char smc[];
    __half* Ym  = (__half*)smc;                 // 3 x 64 x YMS
    __half* A_h = Ym + 3 * 64 * YMS;            // 2 x 64 x KHP

    const int tid = threadIdx.x, w = tid >> 5, lane = tid & 31;
    const int g = lane >> 2, c = lane & 3;
    const int p0 = blockIdx.x * 16;
    const __half* yhb = yh + ((size_t)(p0 >> 10) << 10) * 128;  // batch base

    // zero A_h (K-pad cols must stay 0)
    for (int i = tid; i < 2 * 64 * (KHP / 2); i += 128) ((uint32_t*)A_h)[i] = 0;
    __syncthreads();

    // gather(0), gather(1): 64 rows x 16 cp16 each (fp16 rows, 256 B)
    #pragma unroll
    for (int j = 0; j < 8; j++) {
        int idx = tid + j * 128;
        int row = idx >> 4, col = (idx & 15) << 3;
        int nb = __ldg(nbrs + (size_t)p0 * 64 + row);
        cp16(Ym + row * YMS + col, yhb + (size_t)nb * 128 + col);
    }
    CP_COMMIT();
    #pragma unroll
    for (int j = 0; j < 8; j++) {
        int idx = tid + j * 128;
        int row = idx >> 4, col = (idx & 15) << 3;
        int nb = __ldg(nbrs + (size_t)(p0 + 1) * 64 + row);
        cp16(Ym + 64 * YMS + row * YMS + col, yhb + (size_t)nb * 128 + col);
    }
    CP_COMMIT();

    // A_h[0] = half(f_ij(0) * mask(0))
    {
        const float* fp = fij + (size_t)p0 * 3200;
        for (int i = tid; i < 1600; i += 128) {
            int n = i / 25, s2 = i - n * 25;
            float2 v = *(const float2*)(fp + i * 2);
            float mkv = __ldg(mask + (size_t)p0 * 64 + n);
            *(__half2*)(A_h + n * KHP + s2 * 2) = __floats2half2_rn(v.x * mkv, v.y * mkv);
        }
    }

    for (int it = 0; it < 16; it++) {
        const int cur = it & 1, nxt = cur ^ 1;
        const int p = p0 + it;

        CP_WAIT(1);          // gather(it) done (gather(it+1) in flight)
        __syncthreads();     // Ym[it%3], A_h[cur] visible; buffers to reuse free

        // issue gather(it+2)
        if (it + 2 < 16) {
            __half* Yn = Ym + ((it + 2) % 3) * 64 * YMS;
            #pragma unroll
            for (int j = 0; j < 8; j++) {
                int idx = tid + j * 128;
                int row = idx >> 4, col = (idx & 15) << 3;
                int nb = __ldg(nbrs + (size_t)(p + 2) * 64 + row);
                cp16(Yn + row * YMS + col, yhb + (size_t)nb * 128 + col);
            }
        }
        CP_COMMIT();

        // stage f_ij(it+1) into registers (latency hidden by MMA)
        float2 rf[13];
        if (it < 15) {
            const float* fp = fij + (size_t)(p + 1) * 3200;
            #pragma unroll
            for (int j = 0; j < 13; j++) {
                int i2 = tid + j * 128;
                if (i2 < 1600) rf[j] = *(const float2*)(fp + i2 * 2);
            }
        }

        // MMA: Wf = A_h[cur] @ G^T  (m64 rows; warp cols w*32..w*32+31)
        float acc[4][4][4];
        #pragma unroll
        for (int m = 0; m < 4; m++)
            #pragma unroll
            for (int nt = 0; nt < 4; nt++)
                acc[m][nt][0] = acc[m][nt][1] = acc[m][nt][2] = acc[m][nt][3] = 0.f;
        {
            const __half* Ah = A_h + cur * 64 * KHP;
            #pragma unroll
            for (int k = 0; k < 4; k++) {
                const int kc = k * 16 + c * 2;
                uint32_t b0[4], b1[4];
                #pragma unroll
                for (int nt = 0; nt < 4; nt++) {
                    const int col = w * 32 + nt * 8 + g;
                    b0[nt] = __ldg((const uint32_t*)(g_Gt + col * KHP + kc));
                    b1[nt] = __ldg((const uint32_t*)(g_Gt + col * KHP + kc + 8));
                }
                #pragma unroll
                for (int m = 0; m < 4; m++) {
                    const __half* ar0 = Ah + (m * 16 + g) * KHP + kc;
                    const __half* ar1 = Ah + (m * 16 + g + 8) * KHP + kc;
                    uint32_t a0 = *(const uint32_t*)ar0;
                    uint32_t a1 = *(const uint32_t*)ar1;
                    uint32_t a2 = *(const uint32_t*)(ar0 + 8);
                    uint32_t a3 = *(const uint32_t*)(ar1 + 8);
                    #pragma unroll
                    for (int nt = 0; nt < 4; nt++)
                        mma_f16(acc[m][nt], a0, a1, a2, a3, b0[nt], b1[nt]);
                }
            }
        }

        // store staged f_ij(it+1) masked -> A_h[nxt]
        if (it < 15) {
            __half* An = A_h + nxt * 64 * KHP;
            #pragma unroll
            for (int j = 0; j < 13; j++) {
                int i2 = tid + j * 128;
                if (i2 < 1600) {
                    int n = i2 / 25, s2 = i2 - n * 25;
                    float mkv = __ldg(mask + (size_t)(p + 1) * 64 + n);
                    *(__half2*)(An + n * KHP + s2 * 2) =
                        __floats2half2_rn(rf[j].x * mkv, rf[j].y * mkv);
                }
            }
        }

        // epilogue: y2[f] = sum_n Wf[n,f] * yh[nbr[n],f]
        const __half* Yc = Ym + (it % 3) * 64 * YMS;
        #pragma unroll
        for (int nt = 0; nt < 4; nt++) {
            const int f0 = w * 32 + nt * 8 + c * 2;
            float s0 = 0.f, s1 = 0.f;
            #pragma unroll
            for (int m = 0; m < 4; m++) {
                float2 v0 = __half22float2(*(const __half2*)(Yc + (m * 16 + g)     * YMS + f0));
                float2 v1 = __half22float2(*(const __half2*)(Yc + (m * 16 + g + 8) * YMS + f0));
                s0 += acc[m][nt][0] * v0.x + acc[m][nt][2] * v1.x;
                s1 += acc[m][nt][1] * v0.y + acc[m][nt][3] * v1.y;
            }
            s0 += __shfl_xor_sync(0xffffffffu, s0, 16);
            s0 += __shfl_xor_sync(0xffffffffu, s0, 8);
            s0 += __shfl_xor_sync(0xffffffffu, s0, 4);
            s1 += __shfl_xor_sync(0xffffffffu, s1, 16);
            s1 += __shfl_xor_sync(0xffffffffu, s1, 8);
            s1 += __shfl_xor_sync(0xffffffffu, s1, 4);
            if (g == 0) {
                out[(size_t)p * 128 + f0]     = y[(size_t)p * 128 + f0]     + s0;
                out[(size_t)p * 128 + f0 + 1] = y[(size_t)p * 128 + f0 + 1] + s1;
            }
        }
    }
}

// ---------------------------------------------------------------------------
extern "C" void kernel_launch(void* const* d_in, const int* in_sizes, int n_in,
                              void* d_out, int out_size)
{
    const float* x       = (const float*)d_in[0];
    const int*   nbrs    = (const int*)  d_in[2];
    const float* nmask   = (const float*)d_in[3];
    const float* fij     = (const float*)d_in[4];
    const float* in2f_W  = (const float*)d_in[5];
    const float* in2f_b  = (const float*)d_in[6];
    const float* G_W     = (const float*)d_in[7];
    const float* res_Ws  = (const float*)d_in[8];
    const float* res_bs  = (const float*)d_in[9];
    const float* dense_W = (const float*)d_in[10];
    const float* dense_b = (const float*)d_in[11];
    const float* mask_p  = (const float*)d_in[12];
    float* out = (float*)d_out;

    float  *y, *z;
    __half *yh;
    cudaGetSymbolAddress((void**)&y,  g_y);
    cudaGetSymbolAddress((void**)&z,  g_z);
    cudaGetSymbolAddress((void**)&yh, g_yh);

    const int smem_d    = 16 * APD * sizeof(float);                      // 8.4 KB
    const int smem_conv = 3 * 64 * YMS * 2 + 2 * 64 * KHP * 2;           // 70.6 KB

    cudaFuncSetAttribute(conv_kernel, cudaFuncAttributeMaxDynamicSharedMemorySize, smem_conv);

    prep_kernel<<<(128 * KHP + 255) / 256, 256>>>(G_W);
    in2f_kernel<<<BA / 16, 128, smem_d>>>(x, in2f_W, in2f_b, y, yh);
    conv_kernel<<<BA / 16, 128, smem_conv>>>(y, yh, nbrs, nmask, fij, z);
    mlp_kernel<<<BA / 16, 128, smem_d>>>(z, res_Ws, res_bs, dense_W, dense_b,
                                         mask_p, x, out);
}